// round 2
// baseline (speedup 1.0000x reference)
#include <cuda_runtime.h>
#include <cstdint>

// Problem dims
#define Bn 8
#define Cn 16
#define Dn 192
#define OCn 4
#define OHn 50
#define OWn 200
#define Kbig (Cn*Dn)   // 3072

// Scratch (device globals — no runtime allocation allowed)
__device__ float g_Rt[Cn*Cn*Dn*Dn];                    //  37.7 MB  Rt[i][(j,q)][n] = R[i][j][n][q]
__device__ float g_t [(size_t)Bn*Cn*Dn*Kbig];          // 302   MB  t[b,i][m][(j,q)]
__device__ float g_y [(size_t)Bn*Cn*Dn*Dn];            //  18.9 MB  y[b,i][m][n]
__device__ float g_u [(size_t)Bn*OCn*OHn*Kbig];        //  19.7 MB  u[b,i][m][(j,q)]

// ---------------------------------------------------------------------------
// Transpose each 192x192 matrix of R:  Rt[i][j][q][n] = R[i][j][n][q]
// ---------------------------------------------------------------------------
__global__ void k_transpose(const float* __restrict__ R) {
    __shared__ float tile[32][33];
    const int mat = blockIdx.z;                       // i*Cn + j  (256 mats)
    const float* __restrict__ src = R    + (size_t)mat * Dn * Dn;
    float* __restrict__       dst = g_Rt + (size_t)mat * Dn * Dn;
    const int x0 = blockIdx.x * 32, y0 = blockIdx.y * 32;
    const int tx = threadIdx.x, ty = threadIdx.y;     // 32 x 8
    #pragma unroll
    for (int r = 0; r < 32; r += 8)
        tile[ty + r][tx] = src[(size_t)(y0 + ty + r) * Dn + x0 + tx];
    __syncthreads();
    #pragma unroll
    for (int r = 0; r < 32; r += 8)
        dst[(size_t)(x0 + ty + r) * Dn + y0 + tx] = tile[tx][ty + r];
}

// ---------------------------------------------------------------------------
// Generic 64x64x16 tiled SGEMM body: C = A[MxK] * B[KxN]  (row-major, NN)
// 256 threads, 4x4 micro-tile per thread. K must be a multiple of 16
// (all K here are 192 or 3072). M/N predicated.
// ---------------------------------------------------------------------------
__device__ __forceinline__ void sgemm64(
    const float* __restrict__ A, int lda,
    const float* __restrict__ Bp, int ldb,
    float* __restrict__ Cp, int ldc,
    int M, int N, int K)
{
    __shared__ float As[16][68];   // [k][m], padded to kill STS conflicts, float4-aligned rows
    __shared__ float Bs[16][64];   // [k][n]

    const int tid = threadIdx.x;
    const int tx  = tid & 15;      // 0..15 -> 4 output cols
    const int ty  = tid >> 4;      // 0..15 -> 4 output rows
    const int row0 = blockIdx.y * 64;
    const int col0 = blockIdx.x * 64;

    const int a_k = tid & 15;      // k index for A loads (coalesced along K)
    const int a_r = tid >> 4;      // row base
    const int b_n = tid & 63;      // n index for B loads (coalesced along N)
    const int b_k = tid >> 6;      // k base

    float acc[4][4] = {};

    for (int kt = 0; kt < K; kt += 16) {
        #pragma unroll
        for (int p = 0; p < 4; ++p) {
            int r  = a_r + p * 16;
            int gr = row0 + r;
            As[a_k][r] = (gr < M) ? A[(size_t)gr * lda + kt + a_k] : 0.f;
        }
        #pragma unroll
        for (int p = 0; p < 4; ++p) {
            int kk = b_k + p * 4;
            int gc = col0 + b_n;
            Bs[kk][b_n] = (gc < N) ? Bp[(size_t)(kt + kk) * ldb + gc] : 0.f;
        }
        __syncthreads();

        #pragma unroll
        for (int kk = 0; kk < 16; ++kk) {
            float4 a4 = *reinterpret_cast<const float4*>(&As[kk][ty * 4]);
            float4 b4 = *reinterpret_cast<const float4*>(&Bs[kk][tx * 4]);
            float a[4] = {a4.x, a4.y, a4.z, a4.w};
            float b[4] = {b4.x, b4.y, b4.z, b4.w};
            #pragma unroll
            for (int i = 0; i < 4; ++i)
                #pragma unroll
                for (int j = 0; j < 4; ++j)
                    acc[i][j] = fmaf(a[i], b[j], acc[i][j]);
        }
        __syncthreads();
    }

    #pragma unroll
    for (int i = 0; i < 4; ++i) {
        int gr = row0 + ty * 4 + i;
        if (gr >= M) continue;
        #pragma unroll
        for (int j = 0; j < 4; ++j) {
            int gc = col0 + tx * 4 + j;
            if (gc < N) Cp[(size_t)gr * ldc + gc] = acc[i][j];
        }
    }
}

// ---------------------------------------------------------------------------
// Stage A1:  t[b,i][m][(j,q)] = R[i,j] @ x[b,j]       (2048 x 192^3 GEMMs)
// ---------------------------------------------------------------------------
__global__ void __launch_bounds__(256) k_gemm_A1(const float* __restrict__ R,
                                                 const float* __restrict__ x) {
    const int z = blockIdx.z;
    const int j = z % Cn;
    const int i = (z / Cn) % Cn;
    const int b = z / (Cn * Cn);
    const float* A  = R   + (size_t)(i * Cn + j) * Dn * Dn;
    const float* Bp = x   + (size_t)(b * Cn + j) * Dn * Dn;
    float*       Cp = g_t + (size_t)(b * Cn + i) * Dn * Kbig + (size_t)j * Dn;
    sgemm64(A, Dn, Bp, Dn, Cp, Kbig, Dn, Dn, Dn);
}

// ---------------------------------------------------------------------------
// Stage A2:  y[b,i] = t[b,i] [192x3072] @ Rt[i] [3072x192]   (j folded into K)
// ---------------------------------------------------------------------------
__global__ void __launch_bounds__(256) k_gemm_A2() {
    const int z = blockIdx.z;                 // b*Cn + i
    const int i = z % Cn;
    const float* A  = g_t  + (size_t)z * Dn * Kbig;
    const float* Bp = g_Rt + (size_t)i * Cn * Dn * Dn;
    float*       Cp = g_y  + (size_t)z * Dn * Dn;
    sgemm64(A, Kbig, Bp, Dn, Cp, Dn, Dn, Dn, Kbig);
}

// ---------------------------------------------------------------------------
// Stage B1:  u[b,i][m][(j,q)] = P[i,j] @ y[b,j]        (512 x 50x192x192)
// ---------------------------------------------------------------------------
__global__ void __launch_bounds__(256) k_gemm_B1(const float* __restrict__ P) {
    const int z = blockIdx.z;                 // (b*OCn + i)*Cn + j
    const int j = z % Cn;
    const int i = (z / Cn) % OCn;
    const int b = z / (Cn * OCn);
    const float* A  = P   + (size_t)(i * Cn + j) * OHn * Dn;
    const float* Bp = g_y + (size_t)(b * Cn + j) * Dn * Dn;
    float*       Cp = g_u + (size_t)(b * OCn + i) * OHn * Kbig + (size_t)j * Dn;
    sgemm64(A, Dn, Bp, Dn, Cp, Kbig, OHn, Dn, Dn);
}

// ---------------------------------------------------------------------------
// Stage B2:  out[b,i] = u[b,i] [50x3072] @ PT[i] [3072x200]  (PT already K-major stacked)
// ---------------------------------------------------------------------------
__global__ void __launch_bounds__(256) k_gemm_B2(const float* __restrict__ PT,
                                                 float* __restrict__ out) {
    const int z = blockIdx.z;                 // b*OCn + i
    const int i = z % OCn;
    const float* A  = g_u + (size_t)z * OHn * Kbig;
    const float* Bp = PT  + (size_t)i * Cn * Dn * OWn;
    float*       Cp = out + (size_t)z * OHn * OWn;
    sgemm64(A, Kbig, Bp, OWn, Cp, OWn, OHn, OWn, Kbig);
}

// ---------------------------------------------------------------------------
extern "C" void kernel_launch(void* const* d_in, const int* in_sizes, int n_in,
                              void* d_out, int out_size) {
    const float* x  = (const float*)d_in[0];
    const float* R  = (const float*)d_in[1];
    const float* P  = (const float*)d_in[2];
    const float* PT = (const float*)d_in[3];
    float* out = (float*)d_out;

    k_transpose<<<dim3(6, 6, 256), dim3(32, 8)>>>(R);
    k_gemm_A1<<<dim3(3, 3, Bn * Cn * Cn), 256>>>(R, x);
    k_gemm_A2<<<dim3(3, 3, Bn * Cn), 256>>>();
    k_gemm_B1<<<dim3(3, 1, Bn * OCn * Cn), 256>>>(P);
    k_gemm_B2<<<dim3(4, 1, Bn * OCn), 256>>>(PT, out);
}

// round 3
// speedup vs baseline: 1.7804x; 1.7804x over previous
#include <cuda_runtime.h>
#include <cuda_bf16.h>
#include <cstdint>

// Problem dims
#define Bn 8
#define Cn 16
#define Dn 192
#define OCn 4
#define OHn 50
#define OWn 200
#define Kbig (Cn*Dn)   // 3072

// GEMM tile config
#define BM 128
#define BN 64
#define BK 32
#define APAD 8   // A smem row pad (stride 40 bf16) -> conflict-free ldmatrix
#define BPAD 8   // B smem row pad (stride 72 bf16)

// Scratch (device globals — no runtime allocation allowed)
__device__ float g_Rt[Cn*Cn*Dn*Dn];                    //  Rt[i][(j,q)][n] = R[i][j][n][q]
__device__ float g_t [(size_t)Bn*Cn*Dn*Kbig];          //  t[b,i][m][(j,q)]
__device__ float g_y [(size_t)Bn*Cn*Dn*Dn];            //  y[b,i][m][n]
__device__ float g_u [(size_t)Bn*OCn*OHn*Kbig];        //  u[b,i][m][(j,q)]

// ---------------------------------------------------------------------------
// Transpose each 192x192 matrix of R:  Rt[i][j][q][n] = R[i][j][n][q]
// ---------------------------------------------------------------------------
__global__ void k_transpose(const float* __restrict__ R) {
    __shared__ float tile[32][33];
    const int mat = blockIdx.z;
    const float* __restrict__ src = R    + (size_t)mat * Dn * Dn;
    float* __restrict__       dst = g_Rt + (size_t)mat * Dn * Dn;
    const int x0 = blockIdx.x * 32, y0 = blockIdx.y * 32;
    const int tx = threadIdx.x, ty = threadIdx.y;     // 32 x 8
    #pragma unroll
    for (int r = 0; r < 32; r += 8)
        tile[ty + r][tx] = src[(size_t)(y0 + ty + r) * Dn + x0 + tx];
    __syncthreads();
    #pragma unroll
    for (int r = 0; r < 32; r += 8)
        dst[(size_t)(x0 + ty + r) * Dn + y0 + tx] = tile[tx][ty + r];
}

// ---------------------------------------------------------------------------
// bf16x3 helpers
// ---------------------------------------------------------------------------
__device__ __forceinline__ void f2bf(float v, __nv_bfloat16& h, __nv_bfloat16& l) {
    h = __float2bfloat16_rn(v);
    l = __float2bfloat16_rn(v - __bfloat162float(h));
}

__device__ __forceinline__ void mma_bf16(float* c, const unsigned* a, const unsigned* b) {
    asm volatile(
        "mma.sync.aligned.m16n8k16.row.col.f32.bf16.bf16.f32 "
        "{%0,%1,%2,%3}, {%4,%5,%6,%7}, {%8,%9}, {%0,%1,%2,%3};\n"
        : "+f"(c[0]), "+f"(c[1]), "+f"(c[2]), "+f"(c[3])
        : "r"(a[0]), "r"(a[1]), "r"(a[2]), "r"(a[3]), "r"(b[0]), "r"(b[1]));
}

__device__ __forceinline__ void ldsm4(unsigned* r, unsigned addr) {
    asm volatile("ldmatrix.sync.aligned.m8n8.x4.shared.b16 {%0,%1,%2,%3}, [%4];\n"
                 : "=r"(r[0]), "=r"(r[1]), "=r"(r[2]), "=r"(r[3]) : "r"(addr));
}
__device__ __forceinline__ void ldsm4t(unsigned* r, unsigned addr) {
    asm volatile("ldmatrix.sync.aligned.m8n8.x4.trans.shared.b16 {%0,%1,%2,%3}, [%4];\n"
                 : "=r"(r[0]), "=r"(r[1]), "=r"(r[2]), "=r"(r[3]) : "r"(addr));
}

// ---------------------------------------------------------------------------
// Tensor-core bf16x3 GEMM body: C = A[MxK] * B[KxN], fp32 in/out, NN row-major.
// Block 128x64, 256 threads (8 warps as 4x2, warp tile 32x32), BK=32.
// K must be a multiple of 32 (here 192 or 3072). M/N predicated; N mult of 4.
// ---------------------------------------------------------------------------
__device__ __forceinline__ void bgemm(
    const float* __restrict__ A, int lda,
    const float* __restrict__ Bp, int ldb,
    float* __restrict__ Cp, int ldc,
    int M, int N, int K)
{
    __shared__ __nv_bfloat16 sAh[BM][BK + APAD];
    __shared__ __nv_bfloat16 sAl[BM][BK + APAD];
    __shared__ __nv_bfloat16 sBh[BK][BN + BPAD];
    __shared__ __nv_bfloat16 sBl[BK][BN + BPAD];

    const int tid  = threadIdx.x;
    const int lane = tid & 31;
    const int warp = tid >> 5;
    const int wm = warp & 3;          // m-warp 0..3
    const int wn = warp >> 2;         // n-warp 0..1
    const int row0 = blockIdx.y * BM;
    const int col0 = blockIdx.x * BN;

    // gmem load mappings (float4-coalesced)
    const int ar = tid >> 3;          // A: row 0..31 (+32p), 8 thr/row
    const int ac = (tid & 7) * 4;     // A: k col
    const int br = tid >> 4;          // B: k row 0..15 (+16p)
    const int bc = (tid & 15) * 4;    // B: n col

    float acc[2][4][4];
    #pragma unroll
    for (int t = 0; t < 2; ++t)
        #pragma unroll
        for (int n = 0; n < 4; ++n)
            #pragma unroll
            for (int e = 0; e < 4; ++e) acc[t][n][e] = 0.f;

    // ldmatrix source addresses (k-chunk 0; chunk 1 adds a fixed byte offset)
    unsigned aAdH[2], aAdL[2], bAdH[2], bAdL[2];
    #pragma unroll
    for (int t = 0; t < 2; ++t) {
        int rr = wm * 32 + t * 16 + (lane & 15);
        int cc = (lane >> 4) * 8;
        aAdH[t] = (unsigned)__cvta_generic_to_shared(&sAh[rr][cc]);
        aAdL[t] = (unsigned)__cvta_generic_to_shared(&sAl[rr][cc]);
    }
    #pragma unroll
    for (int p = 0; p < 2; ++p) {
        int rr = (lane & 15);
        int cc = wn * 32 + p * 16 + (lane >> 4) * 8;
        bAdH[p] = (unsigned)__cvta_generic_to_shared(&sBh[rr][cc]);
        bAdL[p] = (unsigned)__cvta_generic_to_shared(&sBl[rr][cc]);
    }
    const unsigned aK1 = 16u * 2u;                  // +16 bf16 along row
    const unsigned bK1 = 16u * (BN + BPAD) * 2u;    // +16 k-rows

    for (int kt = 0; kt < K; kt += BK) {
        // ---- load A tile (128x32 fp32 -> hi/lo bf16) ----
        #pragma unroll
        for (int p = 0; p < 4; ++p) {
            int r  = ar + p * 32;
            int gr = row0 + r;
            float4 v = make_float4(0.f, 0.f, 0.f, 0.f);
            if (gr < M) v = *reinterpret_cast<const float4*>(&A[(size_t)gr * lda + kt + ac]);
            __nv_bfloat16 h0,l0,h1,l1,h2,l2,h3,l3;
            f2bf(v.x, h0, l0); f2bf(v.y, h1, l1);
            f2bf(v.z, h2, l2); f2bf(v.w, h3, l3);
            __nv_bfloat162 q;
            q.x = h0; q.y = h1; *reinterpret_cast<__nv_bfloat162*>(&sAh[r][ac])     = q;
            q.x = h2; q.y = h3; *reinterpret_cast<__nv_bfloat162*>(&sAh[r][ac + 2]) = q;
            q.x = l0; q.y = l1; *reinterpret_cast<__nv_bfloat162*>(&sAl[r][ac])     = q;
            q.x = l2; q.y = l3; *reinterpret_cast<__nv_bfloat162*>(&sAl[r][ac + 2]) = q;
        }
        // ---- load B tile (32x64 fp32 -> hi/lo bf16) ----
        #pragma unroll
        for (int p = 0; p < 2; ++p) {
            int r  = br + p * 16;
            int gc = col0 + bc;
            float4 v = make_float4(0.f, 0.f, 0.f, 0.f);
            if (gc < N) v = *reinterpret_cast<const float4*>(&Bp[(size_t)(kt + r) * ldb + gc]);
            __nv_bfloat16 h0,l0,h1,l1,h2,l2,h3,l3;
            f2bf(v.x, h0, l0); f2bf(v.y, h1, l1);
            f2bf(v.z, h2, l2); f2bf(v.w, h3, l3);
            __nv_bfloat162 q;
            q.x = h0; q.y = h1; *reinterpret_cast<__nv_bfloat162*>(&sBh[r][bc])     = q;
            q.x = h2; q.y = h3; *reinterpret_cast<__nv_bfloat162*>(&sBh[r][bc + 2]) = q;
            q.x = l0; q.y = l1; *reinterpret_cast<__nv_bfloat162*>(&sBl[r][bc])     = q;
            q.x = l2; q.y = l3; *reinterpret_cast<__nv_bfloat162*>(&sBl[r][bc + 2]) = q;
        }
        __syncthreads();

        // ---- 2 k16 chunks, 3 mma passes each (hi*hi + hi*lo + lo*hi) ----
        #pragma unroll
        for (int kk = 0; kk < 2; ++kk) {
            unsigned ah[2][4], al[2][4], bh[2][4], bl[2][4];
            #pragma unroll
            for (int t = 0; t < 2; ++t) {
                ldsm4(ah[t], aAdH[t] + kk * aK1);
                ldsm4(al[t], aAdL[t] + kk * aK1);
            }
            #pragma unroll
            for (int p = 0; p < 2; ++p) {
                ldsm4t(bh[p], bAdH[p] + kk * bK1);
                ldsm4t(bl[p], bAdL[p] + kk * bK1);
            }
            #pragma unroll
            for (int t = 0; t < 2; ++t) {
                #pragma unroll
                for (int nt = 0; nt < 4; ++nt) {
                    const unsigned* Bh = &bh[nt >> 1][(nt & 1) * 2];
                    const unsigned* Bl = &bl[nt >> 1][(nt & 1) * 2];
                    mma_bf16(acc[t][nt], ah[t], Bh);   // hi*hi
                    mma_bf16(acc[t][nt], ah[t], Bl);   // hi*lo
                    mma_bf16(acc[t][nt], al[t], Bh);   // lo*hi
                }
            }
        }
        __syncthreads();
    }

    // ---- epilogue (fp32) ----
    #pragma unroll
    for (int t = 0; t < 2; ++t) {
        int mB = row0 + wm * 32 + t * 16 + (lane >> 2);
        #pragma unroll
        for (int nt = 0; nt < 4; ++nt) {
            int nB = col0 + wn * 32 + nt * 8 + (lane & 3) * 2;
            float* c = acc[t][nt];
            if (mB < M) {
                if (nB     < N) Cp[(size_t)mB * ldc + nB]     = c[0];
                if (nB + 1 < N) Cp[(size_t)mB * ldc + nB + 1] = c[1];
            }
            if (mB + 8 < M) {
                if (nB     < N) Cp[(size_t)(mB + 8) * ldc + nB]     = c[2];
                if (nB + 1 < N) Cp[(size_t)(mB + 8) * ldc + nB + 1] = c[3];
            }
        }
    }
}

// ---------------------------------------------------------------------------
// Stage A1:  t[b,i][m][(j,q)] = R[i,j] @ x[b,j]
// ---------------------------------------------------------------------------
__global__ void __launch_bounds__(256) k_gemm_A1(const float* __restrict__ R,
                                                 const float* __restrict__ x) {
    const int z = blockIdx.z;
    const int j = z % Cn;
    const int i = (z / Cn) % Cn;
    const int b = z / (Cn * Cn);
    const float* A  = R   + (size_t)(i * Cn + j) * Dn * Dn;
    const float* Bp = x   + (size_t)(b * Cn + j) * Dn * Dn;
    float*       Cp = g_t + (size_t)(b * Cn + i) * Dn * Kbig + (size_t)j * Dn;
    bgemm(A, Dn, Bp, Dn, Cp, Kbig, Dn, Dn, Dn);
}

// ---------------------------------------------------------------------------
// Stage A2:  y[b,i] = t[b,i] [192x3072] @ Rt[i] [3072x192]
// ---------------------------------------------------------------------------
__global__ void __launch_bounds__(256) k_gemm_A2() {
    const int z = blockIdx.z;                 // b*Cn + i
    const int i = z % Cn;
    const float* A  = g_t  + (size_t)z * Dn * Kbig;
    const float* Bp = g_Rt + (size_t)i * Cn * Dn * Dn;
    float*       Cp = g_y  + (size_t)z * Dn * Dn;
    bgemm(A, Kbig, Bp, Dn, Cp, Dn, Dn, Dn, Kbig);
}

// ---------------------------------------------------------------------------
// Stage B1:  u[b,i][m][(j,q)] = P[i,j] @ y[b,j]
// ---------------------------------------------------------------------------
__global__ void __launch_bounds__(256) k_gemm_B1(const float* __restrict__ P) {
    const int z = blockIdx.z;                 // (b*OCn + i)*Cn + j
    const int j = z % Cn;
    const int i = (z / Cn) % OCn;
    const int b = z / (Cn * OCn);
    const float* A  = P   + (size_t)(i * Cn + j) * OHn * Dn;
    const float* Bp = g_y + (size_t)(b * Cn + j) * Dn * Dn;
    float*       Cp = g_u + (size_t)(b * OCn + i) * OHn * Kbig + (size_t)j * Dn;
    bgemm(A, Dn, Bp, Dn, Cp, Kbig, OHn, Dn, Dn);
}

// ---------------------------------------------------------------------------
// Stage B2:  out[b,i] = u[b,i] [50x3072] @ PT[i] [3072x200]
// ---------------------------------------------------------------------------
__global__ void __launch_bounds__(256) k_gemm_B2(const float* __restrict__ PT,
                                                 float* __restrict__ out) {
    const int z = blockIdx.z;                 // b*OCn + i
    const int i = z % OCn;
    const float* A  = g_u + (size_t)z * OHn * Kbig;
    const float* Bp = PT  + (size_t)i * Cn * Dn * OWn;
    float*       Cp = out + (size_t)z * OHn * OWn;
    bgemm(A, Kbig, Bp, OWn, Cp, OWn, OHn, OWn, Kbig);
}

// ---------------------------------------------------------------------------
extern "C" void kernel_launch(void* const* d_in, const int* in_sizes, int n_in,
                              void* d_out, int out_size) {
    const float* x  = (const float*)d_in[0];
    const float* R  = (const float*)d_in[1];
    const float* P  = (const float*)d_in[2];
    const float* PT = (const float*)d_in[3];
    float* out = (float*)d_out;

    k_transpose<<<dim3(6, 6, 256), dim3(32, 8)>>>(R);
    k_gemm_A1<<<dim3(3, 2, Bn * Cn * Cn), 256>>>(R, x);
    k_gemm_A2<<<dim3(3, 2, Bn * Cn), 256>>>();
    k_gemm_B1<<<dim3(3, 1, Bn * OCn * Cn), 256>>>(P);
    k_gemm_B2<<<dim3(4, 1, Bn * OCn), 256>>>(PT, out);
}